// round 4
// baseline (speedup 1.0000x reference)
#include <cuda_runtime.h>

#define NW 6
#define NL 4
#define HP 112
#define WP 112
#define NB 8
#define OC 16

__device__ float g_T[6*27];
__device__ float g_aux[50];   // [0..35] Q=W^T W, [36..41] L=W^T b, [42..47] A=colmean(W), [48] bbar, [49] S=sum b^2

// ---------------------------------------------------------------------------
// Kernel 0: one warp per basis state, warp-local sync. Each layer = 6 single-
// qubit butterflies + ONE composite index permutation (CNOT ring is GF(2)-
// linear). Then M_w -> fold (-i)^popcount -> 27-term trig table. Also builds
// the LayerNorm quadratic-form tables from fcw/fcb.
// ---------------------------------------------------------------------------
__global__ void k_precompute(const float* __restrict__ w,
                             const float* __restrict__ fcw,
                             const float* __restrict__ fcb)
{
    __shared__ float2 sU[24][4];
    __shared__ float2 phi[8][64];
    __shared__ float  Mre[6][8][8];
    __shared__ float  Mim[6][8][8];

    const int tid  = threadIdx.x;         // 256 threads = 8 warps
    const int wrp  = tid >> 5;
    const int lane = tid & 31;

    // LayerNorm aux tables (independent of circuit, no sync needed)
    if (tid >= 64 && tid < 100) {
        const int e = tid - 64, i = e / 6, j = e % 6;
        float acc = 0.f;
        #pragma unroll
        for (int o = 0; o < OC; o++) acc += fcw[o*6+i] * fcw[o*6+j];
        g_aux[e] = acc;
    } else if (tid >= 100 && tid < 106) {
        const int i = tid - 100;
        float acc = 0.f;
        #pragma unroll
        for (int o = 0; o < OC; o++) acc += fcw[o*6+i] * fcb[o];
        g_aux[36 + i] = acc;
    } else if (tid >= 106 && tid < 112) {
        const int i = tid - 106;
        float acc = 0.f;
        #pragma unroll
        for (int o = 0; o < OC; o++) acc += fcw[o*6+i];
        g_aux[42 + i] = acc * (1.f / OC);
    } else if (tid == 112) {
        float acc = 0.f;
        #pragma unroll
        for (int o = 0; o < OC; o++) acc += fcb[o];
        g_aux[48] = acc * (1.f / OC);
    } else if (tid == 113) {
        float acc = 0.f;
        #pragma unroll
        for (int o = 0; o < OC; o++) acc += fcb[o] * fcb[o];
        g_aux[49] = acc;
    }

    if (tid < 24) {
        const float ph = w[tid*3 + 0];
        const float th = w[tid*3 + 1];
        const float om = w[tid*3 + 2];
        const float ch = cosf(0.5f * th), sh = sinf(0.5f * th);
        float cp, sp, cm, sm;
        sincosf(-0.5f * (ph + om), &sp, &cp);
        sincosf(-0.5f * (ph - om), &sm, &cm);
        sU[tid][0] = make_float2( cp*ch,  sp*ch);
        sU[tid][1] = make_float2(-cm*sh,  sm*sh);
        sU[tid][2] = make_float2( cm*sh,  sm*sh);
        sU[tid][3] = make_float2( cp*ch, -sp*ch);
    }
    {
        const int s0 = lane, s1 = lane + 32;
        phi[wrp][s0] = make_float2((s0 == wrp * 8) ? 1.f : 0.f, 0.f);
        phi[wrp][s1] = make_float2((s1 == wrp * 8) ? 1.f : 0.f, 0.f);
    }
    __syncthreads();

    float2* st = phi[wrp];
    for (int l = 0; l < NL; l++) {
        #pragma unroll
        for (int q = 0; q < NW; q++) {
            const int stride = 1 << (5 - q);
            const int s0 = ((lane & ~(stride - 1)) << 1) | (lane & (stride - 1));
            const int s1 = s0 | stride;
            const float2 u00 = sU[l*6+q][0], u01 = sU[l*6+q][1];
            const float2 u10 = sU[l*6+q][2], u11 = sU[l*6+q][3];
            const float2 a0 = st[s0], a1 = st[s1];
            st[s0] = make_float2(
                u00.x*a0.x - u00.y*a0.y + u01.x*a1.x - u01.y*a1.y,
                u00.x*a0.y + u00.y*a0.x + u01.x*a1.y + u01.y*a1.x);
            st[s1] = make_float2(
                u10.x*a0.x - u10.y*a0.y + u11.x*a1.x - u11.y*a1.y,
                u10.x*a0.y + u10.y*a0.x + u11.x*a1.y + u11.y*a1.x);
            __syncwarp();
        }
        const int r = l % (NW - 1) + 1;
        int i0 = lane, i1 = lane + 32;
        #pragma unroll
        for (int q = NW - 1; q >= 0; q--) {
            const int cpos = 5 - q;
            const int tpos = 5 - ((q + r) % NW);
            i0 ^= ((i0 >> cpos) & 1) << tpos;
            i1 ^= ((i1 >> cpos) & 1) << tpos;
        }
        const float2 v0 = st[i0], v1 = st[i1];
        __syncwarp();
        st[lane] = v0;
        st[lane + 32] = v1;
        __syncwarp();
    }
    __syncthreads();

    for (int e = tid; e < 6 * 64; e += blockDim.x) {
        const int q = e / 64, ij = e % 64, i = ij / 8, jj = ij % 8;
        float re = 0.f, im = 0.f;
        #pragma unroll 8
        for (int t = 0; t < 64; t++) {
            const float z = ((t >> (5 - q)) & 1) ? -1.f : 1.f;
            const float2 a = phi[i][t], b = phi[jj][t];
            re += z * (a.x * b.x + a.y * b.y);
            im += z * (a.x * b.y - a.y * b.x);
        }
        Mre[q][i][jj] = re;
        Mim[q][i][jj] = im;
    }
    __syncthreads();

    if (tid < 6 * 27) {
        const int q = tid / 27, term = tid % 27;
        const int tt[3] = { term / 9, (term / 3) % 3, term % 3 };
        float acc = 0.f;
        for (int i = 0; i < 8; i++) {
            for (int jj = 0; jj < 8; jj++) {
                const int k = (__popc(i) - __popc(jj)) & 3;
                const float mre = Mre[q][i][jj], mim = Mim[q][i][jj];
                float f = (k == 0) ? mre : (k == 1) ? -mim : (k == 2) ? -mre : mim;
                #pragma unroll
                for (int c = 0; c < 3; c++) {
                    const int bi = (i >> (2 - c)) & 1;
                    const int bj = (jj >> (2 - c)) & 1;
                    const int t = tt[c];
                    float pc;
                    if (bi == bj)
                        pc = (t == 0) ? 0.5f : (t == 1) ? (bi ? -0.5f : 0.5f) : 0.f;
                    else
                        pc = (t == 2) ? 0.5f : 0.f;
                    f *= pc;
                }
                acc += f;
            }
        }
        g_T[tid] = acc;
    }
}

// ---------------------------------------------------------------------------
// Fused kernel: block = 16x16 patch tile.
// Phase 1 : 18x18 halo pixels -> {e[6], mu, inv} in shared (no y[16] regs;
//           LayerNorm stats via quadratic form).
// Phase 1b: 324x16 (pixel,channel) items -> sy[o][18][19] (relu'd LN output).
// Phase 2 : each thread emits 2x2 output quad x 16 channels, coalesced.
// ---------------------------------------------------------------------------
__global__ void __launch_bounds__(256, 3)
k_fused(const float* __restrict__ x,
        const float* __restrict__ fcw,
        const float* __restrict__ fcb,
        const float* __restrict__ lng,
        const float* __restrict__ lnb,
        float* __restrict__ out)
{
    __shared__ float sy[OC][18][19];
    __shared__ float sP[18*18][8];        // e[6], mu, inv per halo pixel
    __shared__ float sT[162], sA[50], sFC[96], sFB[16], sG[16], sB[16];

    const int tid = threadIdx.x;
    if (tid < 162) sT[tid] = g_T[tid];
    if (tid >= 162 && tid < 212) sA[tid - 162] = g_aux[tid - 162];
    if (tid < 96)  sFC[tid] = fcw[tid];
    if (tid >= 96  && tid < 112) sFB[tid - 96]  = fcb[tid - 96];
    if (tid >= 112 && tid < 128) sG [tid - 112] = lng[tid - 112];
    if (tid >= 128 && tid < 144) sB [tid - 128] = lnb[tid - 128];
    __syncthreads();

    const int b   = blockIdx.z;
    const int bh0 = blockIdx.y * 16;
    const int bw0 = blockIdx.x * 16;

    // ---- Phase 1: per halo pixel, compute e[6], mu, inv ----
    for (int i = tid; i < 18 * 18; i += 256) {
        const int r = i / 18, c = i % 18;
        const int hp = min(max(bh0 - 1 + r, 0), HP - 1);
        const int wp = min(max(bw0 - 1 + c, 0), WP - 1);

        float g[3][3];
        #pragma unroll
        for (int ch = 0; ch < 3; ch++) {
            const float* base = x + (((long)(b * 3 + ch) * 224 + 2 * hp) * 224 + 2 * wp);
            const float2 r0 = *reinterpret_cast<const float2*>(base);
            const float2 r1 = *reinterpret_cast<const float2*>(base + 224);
            const float a = 0.25f * (r0.x + r0.y + r1.x + r1.y);
            float sn, cs;
            sincosf(a, &sn, &cs);
            g[ch][0] = 1.f; g[ch][1] = cs; g[ch][2] = sn;
        }

        float e[6];
        #pragma unroll
        for (int q = 0; q < 6; q++) e[q] = 0.f;
        #pragma unroll
        for (int t0 = 0; t0 < 3; t0++)
            #pragma unroll
            for (int t1 = 0; t1 < 3; t1++) {
                const float p01 = g[0][t0] * g[1][t1];
                #pragma unroll
                for (int t2 = 0; t2 < 3; t2++) {
                    const float bas = p01 * g[2][t2];
                    const int t = (t0 * 3 + t1) * 3 + t2;
                    #pragma unroll
                    for (int q = 0; q < 6; q++) e[q] += sT[q * 27 + t] * bas;
                }
            }

        // mu = A.e + bbar ; sum y^2 = e^T Q e + 2 L.e + S
        float mu = sA[48];
        #pragma unroll
        for (int q = 0; q < 6; q++) mu += sA[42 + q] * e[q];
        float s2 = sA[49];
        #pragma unroll
        for (int q = 0; q < 6; q++) {
            float qe = 2.f * sA[36 + q];
            #pragma unroll
            for (int p = 0; p < 6; p++) qe += sA[q * 6 + p] * e[p];
            s2 += e[q] * qe;
        }
        const float var = s2 * (1.f / OC) - mu * mu;
        const float inv = rsqrtf(var + 1e-5f);

        #pragma unroll
        for (int q = 0; q < 6; q++) sP[i][q] = e[q];
        sP[i][6] = mu;
        sP[i][7] = inv;
    }
    __syncthreads();

    // ---- Phase 1b: one y-channel value per work item ----
    for (int i = tid; i < 18 * 18 * OC; i += 256) {
        const int pix = i >> 4, o = i & 15;
        const float* ep = sP[pix];
        float yv = sFB[o];
        #pragma unroll
        for (int q = 0; q < 6; q++) yv += sFC[o * 6 + q] * ep[q];
        const float v = fmaxf((yv - ep[6]) * ep[7] * sG[o] + sB[o], 0.f);
        sy[o][pix / 18][pix % 18] = v;
    }
    __syncthreads();

    // ---- Phase 2: bilinear 2x upsample (jax half-pixel, 0.25/0.75) ----
    const int tx = tid & 15, ty = tid >> 4;
    const int oh = 2 * (bh0 + ty);
    const int ow = 2 * (bw0 + tx);
    const int r0 = ty, r1 = ty + 1, r2 = ty + 2;
    const int c0 = tx, c1 = tx + 1, c2 = tx + 2;

    #pragma unroll
    for (int o = 0; o < OC; o++) {
        const float a0 = 0.25f * sy[o][r0][c0] + 0.75f * sy[o][r0][c1];
        const float b0 = 0.75f * sy[o][r0][c1] + 0.25f * sy[o][r0][c2];
        const float a1 = 0.25f * sy[o][r1][c0] + 0.75f * sy[o][r1][c1];
        const float b1 = 0.75f * sy[o][r1][c1] + 0.25f * sy[o][r1][c2];
        const float a2 = 0.25f * sy[o][r2][c0] + 0.75f * sy[o][r2][c1];
        const float b2 = 0.75f * sy[o][r2][c1] + 0.25f * sy[o][r2][c2];

        float* obase = out + (((long)(b * OC + o) * 224 + oh) * 224 + ow);
        *reinterpret_cast<float2*>(obase) =
            make_float2(0.25f * a0 + 0.75f * a1, 0.25f * b0 + 0.75f * b1);
        *reinterpret_cast<float2*>(obase + 224) =
            make_float2(0.75f * a1 + 0.25f * a2, 0.75f * b1 + 0.25f * b2);
    }
}

extern "C" void kernel_launch(void* const* d_in, const int* in_sizes, int n_in,
                              void* d_out, int out_size)
{
    const float* x   = (const float*)d_in[0];
    const float* wts = (const float*)d_in[1];
    const float* fcw = (const float*)d_in[2];
    const float* fcb = (const float*)d_in[3];
    const float* lng = (const float*)d_in[4];
    const float* lnb = (const float*)d_in[5];
    float* out = (float*)d_out;

    k_precompute<<<1, 256>>>(wts, fcw, fcb);
    dim3 fg(WP / 16, HP / 16, NB);
    k_fused<<<fg, 256>>>(x, fcw, fcb, lng, lnb, out);
}

// round 5
// speedup vs baseline: 1.2786x; 1.2786x over previous
#include <cuda_runtime.h>

#define NW 6
#define NL 4
#define HP 112
#define WP 112
#define NB 8
#define OC 16
#define NPIX (NB*HP*WP)

__device__ float g_T[6*27];
__device__ float g_y[NB*OC*HP*WP];

// ---------------------------------------------------------------------------
// Kernel 0 (v4, register-resident): 8 warps, one basis state each. The 64
// amplitudes live in registers (2 complex per lane). Single-qubit gates:
// stride-32 butterfly = intra-lane reg pair; strides 16..1 = shfl_xor.
// CNOT ring per layer = one composite index permutation (GF(2)-linear),
// realized as a variable-lane shuffle gather. Then M_w = Phi^dag Z_w Phi,
// fold (-i)^popcount phases, emit 27-term trig table.
// ---------------------------------------------------------------------------
__global__ void k_precompute(const float* __restrict__ w)
{
    __shared__ float2 sU[24][4];
    __shared__ float2 phi[8][64];
    __shared__ float  Mre[6][8][8];
    __shared__ float  Mim[6][8][8];

    const int tid  = threadIdx.x;          // 256 threads = 8 warps
    const int wrp  = tid >> 5;
    const int lane = tid & 31;
    const unsigned FULL = 0xFFFFFFFFu;

    if (tid < 24) {
        const float ph = w[tid*3 + 0];
        const float th = w[tid*3 + 1];
        const float om = w[tid*3 + 2];
        const float ch = cosf(0.5f * th), sh = sinf(0.5f * th);
        float cp, sp, cm, sm;
        sincosf(-0.5f * (ph + om), &sp, &cp);   // ep = cp + i sp
        sincosf(-0.5f * (ph - om), &sm, &cm);   // em = cm + i sm
        sU[tid][0] = make_float2( cp*ch,  sp*ch);   // u00
        sU[tid][1] = make_float2(-cm*sh,  sm*sh);   // u01
        sU[tid][2] = make_float2( cm*sh,  sm*sh);   // u10
        sU[tid][3] = make_float2( cp*ch, -sp*ch);   // u11
    }
    __syncthreads();

    // amplitudes: (ar,ai) at s=lane, (br,bi) at s=lane+32
    float ar = (lane == wrp * 8) ? 1.f : 0.f, ai = 0.f;
    float br = (lane + 32 == wrp * 8) ? 1.f : 0.f, bi = 0.f;

    for (int l = 0; l < NL; l++) {
        #pragma unroll
        for (int q = 0; q < NW; q++) {
            const float2 u00 = sU[l*6+q][0], u01 = sU[l*6+q][1];
            const float2 u10 = sU[l*6+q][2], u11 = sU[l*6+q][3];
            if (q == 0) {
                // stride 32: pair is (a, b) within the lane
                const float nar = u00.x*ar - u00.y*ai + u01.x*br - u01.y*bi;
                const float nai = u00.x*ai + u00.y*ar + u01.x*bi + u01.y*br;
                const float nbr = u10.x*ar - u10.y*ai + u11.x*br - u11.y*bi;
                const float nbi = u10.x*ai + u10.y*ar + u11.x*bi + u11.y*br;
                ar = nar; ai = nai; br = nbr; bi = nbi;
            } else {
                const int stride = 1 << (5 - q);      // 16,8,4,2,1
                const float par = __shfl_xor_sync(FULL, ar, stride);
                const float pai = __shfl_xor_sync(FULL, ai, stride);
                const float pbr = __shfl_xor_sync(FULL, br, stride);
                const float pbi = __shfl_xor_sync(FULL, bi, stride);
                const bool hi = (lane & stride) != 0;
                // lo: v' = u00*v + u01*p ; hi: v' = u10*p + u11*v
                {
                    const float v0r = hi ? par : ar, v0i = hi ? pai : ai;
                    const float v1r = hi ? ar : par, v1i = hi ? ai : pai;
                    const float2 cL = hi ? u10 : u00, cR = hi ? u11 : u01;
                    const float nr = cL.x*v0r - cL.y*v0i + cR.x*v1r - cR.y*v1i;
                    const float ni = cL.x*v0i + cL.y*v0r + cR.x*v1i + cR.y*v1r;
                    ar = nr; ai = ni;
                }
                {
                    const float v0r = hi ? pbr : br, v0i = hi ? pbi : bi;
                    const float v1r = hi ? br : pbr, v1i = hi ? bi : pbi;
                    const float2 cL = hi ? u10 : u00, cR = hi ? u11 : u01;
                    const float nr = cL.x*v0r - cL.y*v0i + cR.x*v1r - cR.y*v1i;
                    const float ni = cL.x*v0i + cL.y*v0r + cR.x*v1i + cR.y*v1r;
                    br = nr; bi = ni;
                }
            }
        }
        // CNOT ring composite permutation: new[s] = old[P(s)]
        const int r = l % (NW - 1) + 1;
        int i0 = lane, i1 = lane + 32;
        #pragma unroll
        for (int q = NW - 1; q >= 0; q--) {
            const int cpos = 5 - q;
            const int tpos = 5 - ((q + r) % NW);
            i0 ^= ((i0 >> cpos) & 1) << tpos;
            i1 ^= ((i1 >> cpos) & 1) << tpos;
        }
        // gather via shuffles (do both candidates, select by index bit 5)
        const float g0ar = __shfl_sync(FULL, ar, i0 & 31);
        const float g0ai = __shfl_sync(FULL, ai, i0 & 31);
        const float g0br = __shfl_sync(FULL, br, i0 & 31);
        const float g0bi = __shfl_sync(FULL, bi, i0 & 31);
        const float g1ar = __shfl_sync(FULL, ar, i1 & 31);
        const float g1ai = __shfl_sync(FULL, ai, i1 & 31);
        const float g1br = __shfl_sync(FULL, br, i1 & 31);
        const float g1bi = __shfl_sync(FULL, bi, i1 & 31);
        ar = (i0 < 32) ? g0ar : g0br;
        ai = (i0 < 32) ? g0ai : g0bi;
        br = (i1 < 32) ? g1ar : g1br;
        bi = (i1 < 32) ? g1ai : g1bi;
    }

    phi[wrp][lane]      = make_float2(ar, ai);
    phi[wrp][lane + 32] = make_float2(br, bi);
    __syncthreads();

    // M_w[i][jj] = sum_s z_w(s) conj(phi_i[s]) phi_jj[s]
    for (int e = tid; e < 6 * 64; e += blockDim.x) {
        const int q = e / 64, ij = e % 64, i = ij / 8, jj = ij % 8;
        float re = 0.f, im = 0.f;
        #pragma unroll 8
        for (int t = 0; t < 64; t++) {
            const float z = ((t >> (5 - q)) & 1) ? -1.f : 1.f;
            const float2 a = phi[i][t], b = phi[jj][t];
            re += z * (a.x * b.x + a.y * b.y);
            im += z * (a.x * b.y - a.y * b.x);
        }
        Mre[q][i][jj] = re;
        Mim[q][i][jj] = im;
    }
    __syncthreads();

    // half-angle pair products -> {1, cos a, sin a} basis table
    if (tid < 6 * 27) {
        const int q = tid / 27, term = tid % 27;
        const int tt[3] = { term / 9, (term / 3) % 3, term % 3 };
        float acc = 0.f;
        for (int i = 0; i < 8; i++) {
            for (int jj = 0; jj < 8; jj++) {
                const int k = (__popc(i) - __popc(jj)) & 3;
                const float mre = Mre[q][i][jj], mim = Mim[q][i][jj];
                float f = (k == 0) ? mre : (k == 1) ? -mim : (k == 2) ? -mre : mim;
                #pragma unroll
                for (int c = 0; c < 3; c++) {
                    const int bi = (i >> (2 - c)) & 1;
                    const int bj = (jj >> (2 - c)) & 1;
                    const int t = tt[c];
                    float pc;
                    if (bi == bj)
                        pc = (t == 0) ? 0.5f : (t == 1) ? (bi ? -0.5f : 0.5f) : 0.f;
                    else
                        pc = (t == 2) ? 0.5f : 0.f;
                    f *= pc;
                }
                acc += f;
            }
        }
        g_T[tid] = acc;
    }
}

// ---------------------------------------------------------------------------
// Kernel 1: two adjacent patch pixels per thread (float4 reads, float2
// writes per channel): 2x2 mean -> trig basis -> 6 exps -> FC -> LN -> ReLU.
// ---------------------------------------------------------------------------
__global__ void k_pixels(const float* __restrict__ x,
                         const float* __restrict__ fcw,
                         const float* __restrict__ fcb,
                         const float* __restrict__ lng,
                         const float* __restrict__ lnb)
{
    __shared__ float sT[162], sFC[96], sFB[16], sG[16], sB[16];
    const int tid = threadIdx.x;
    if (tid < 162) sT[tid] = g_T[tid];
    if (tid < 96)  sFC[tid] = fcw[tid];
    if (tid >= 96  && tid < 112) sFB[tid - 96]  = fcb[tid - 96];
    if (tid >= 112 && tid < 128) sG [tid - 112] = lng[tid - 112];
    if (tid >= 128 && tid < 144) sB [tid - 128] = lnb[tid - 128];
    __syncthreads();

    const int pp = blockIdx.x * blockDim.x + tid;
    if (pp >= NPIX / 2) return;
    const int WPH = WP / 2;
    const int b   = pp / (HP * WPH);
    const int rem = pp % (HP * WPH);
    const int hp  = rem / WPH, wpp = rem % WPH;

    float g0[3][3], g1[3][3];
    #pragma unroll
    for (int c = 0; c < 3; c++) {
        const float* base = x + (((long)(b * 3 + c) * 224 + 2 * hp) * 224 + 4 * wpp);
        const float4 r0 = *reinterpret_cast<const float4*>(base);
        const float4 r1 = *reinterpret_cast<const float4*>(base + 224);
        const float a0 = 0.25f * (r0.x + r0.y + r1.x + r1.y);
        const float a1 = 0.25f * (r0.z + r0.w + r1.z + r1.w);
        float sn, cs;
        sincosf(a0, &sn, &cs);
        g0[c][0] = 1.f; g0[c][1] = cs; g0[c][2] = sn;
        sincosf(a1, &sn, &cs);
        g1[c][0] = 1.f; g1[c][1] = cs; g1[c][2] = sn;
    }

    float2 vout[OC];
    #pragma unroll
    for (int half = 0; half < 2; half++) {
        float (*gg)[3] = half ? g1 : g0;

        float e[6];
        #pragma unroll
        for (int q = 0; q < 6; q++) e[q] = 0.f;
        #pragma unroll
        for (int t0 = 0; t0 < 3; t0++)
            #pragma unroll
            for (int t1 = 0; t1 < 3; t1++) {
                const float p01 = gg[0][t0] * gg[1][t1];
                #pragma unroll
                for (int t2 = 0; t2 < 3; t2++) {
                    const float bas = p01 * gg[2][t2];
                    const int t = (t0 * 3 + t1) * 3 + t2;
                    #pragma unroll
                    for (int q = 0; q < 6; q++) e[q] += sT[q * 27 + t] * bas;
                }
            }

        float y[OC], mu = 0.f;
        #pragma unroll
        for (int o = 0; o < OC; o++) {
            float acc = sFB[o];
            #pragma unroll
            for (int q = 0; q < 6; q++) acc += sFC[o * 6 + q] * e[q];
            y[o] = acc;
            mu += acc;
        }
        mu *= (1.f / OC);
        float var = 0.f;
        #pragma unroll
        for (int o = 0; o < OC; o++) { const float d = y[o] - mu; var += d * d; }
        var *= (1.f / OC);
        const float inv = rsqrtf(var + 1e-5f);
        #pragma unroll
        for (int o = 0; o < OC; o++) {
            const float v = fmaxf((y[o] - mu) * inv * sG[o] + sB[o], 0.f);
            if (half) vout[o].y = v; else vout[o].x = v;
        }
    }

    #pragma unroll
    for (int o = 0; o < OC; o++) {
        *reinterpret_cast<float2*>(
            &g_y[(((long)b * OC + o) * HP + hp) * WP + 2 * wpp]) = vout[o];
    }
}

// ---------------------------------------------------------------------------
// Kernel 2: tiled 2x bilinear upsample (jax half-pixel convention).
// Each thread owns one input pixel, produces its 2x2 output quad.
// ---------------------------------------------------------------------------
__global__ void k_resize(float* __restrict__ out)
{
    __shared__ float t[18][19];
    const int bc = blockIdx.z;
    const int ih0 = blockIdx.y * 16 - 1;
    const int iw0 = blockIdx.x * 16 - 1;
    const float* yb = g_y + (long)bc * HP * WP;

    const int tx = threadIdx.x, ty = threadIdx.y;
    const int lin = ty * 16 + tx;
    for (int i = lin; i < 18 * 18; i += 256) {
        const int r = i / 18, c = i % 18;
        const int gr = min(max(ih0 + r, 0), HP - 1);
        const int gc = min(max(iw0 + c, 0), WP - 1);
        t[r][c] = yb[gr * WP + gc];
    }
    __syncthreads();

    const int r0 = ty, r1 = ty + 1, r2 = ty + 2;
    const int c0 = tx, c1 = tx + 1, c2 = tx + 2;
    const float a_0 = 0.25f * t[r0][c0] + 0.75f * t[r0][c1];
    const float b_0 = 0.75f * t[r0][c1] + 0.25f * t[r0][c2];
    const float a_1 = 0.25f * t[r1][c0] + 0.75f * t[r1][c1];
    const float b_1 = 0.75f * t[r1][c1] + 0.25f * t[r1][c2];
    const float a_2 = 0.25f * t[r2][c0] + 0.75f * t[r2][c1];
    const float b_2 = 0.75f * t[r2][c1] + 0.25f * t[r2][c2];

    const int oh = 2 * (blockIdx.y * 16 + ty);
    const int ow = 2 * (blockIdx.x * 16 + tx);
    float* obase = out + ((long)bc * 224 + oh) * 224 + ow;
    *reinterpret_cast<float2*>(obase) =
        make_float2(0.25f * a_0 + 0.75f * a_1, 0.25f * b_0 + 0.75f * b_1);
    *reinterpret_cast<float2*>(obase + 224) =
        make_float2(0.75f * a_1 + 0.25f * a_2, 0.75f * b_1 + 0.25f * b_2);
}

extern "C" void kernel_launch(void* const* d_in, const int* in_sizes, int n_in,
                              void* d_out, int out_size)
{
    const float* x   = (const float*)d_in[0];
    const float* wts = (const float*)d_in[1];
    const float* fcw = (const float*)d_in[2];
    const float* fcb = (const float*)d_in[3];
    const float* lng = (const float*)d_in[4];
    const float* lnb = (const float*)d_in[5];
    float* out = (float*)d_out;

    k_precompute<<<1, 256>>>(wts);
    k_pixels<<<(NPIX/2 + 255) / 256, 256>>>(x, fcw, fcb, lng, lnb);
    dim3 rb(16, 16);
    dim3 rg(WP / 16, HP / 16, NB * OC);
    k_resize<<<rg, rb>>>(out);
}